// round 6
// baseline (speedup 1.0000x reference)
#include <cuda_runtime.h>
#include <cstdint>

// Problem constants
#define NB   64          // batch
#define CC   256         // channels
#define HH   28
#define WW   28
#define PIX  (HH*WW)                 // 784
#define NPIX (NB*PIX)                // 50176
#define TOT  (NB*CC*PIX)             // 12,845,056
#define CW   8                       // 256 channels / 32 bits
#define TH   4                       // rows per conv block
#define OCCH 64                      // output channels per block (oc chunk)
#define NCH  (CC/OCCH)               // 4 chunks
#define NG   (OCCH/4)                // 16 groups of 4 ocs

// ---------------- scratch (device globals; no allocation allowed) --------
__device__ uint32_t g_bits[NB*PIX*CW];            // packed activation signs
__device__ uint32_t g_wb[2][CC*72];               // packed weight signs: [oc][tap][word]
__device__ int      g_pw[2][CC*9];                // popcount of each weight tap
__device__ short    g_y[TOT];                     // integer conv output
__device__ float    g_out1[TOT];                  // stage-1 output (residual for stage 2)
__device__ int                g_sum[2][CC];
__device__ unsigned long long g_sq [2][CC];
__device__ float    g_scale[2][CC], g_shift[2][CC];

// ---------------- zero the stats accumulators ----------------------------
__global__ void zero_kernel() {
    int t = threadIdx.x;            // 256 threads
    g_sum[0][t] = 0; g_sum[1][t] = 0;
    g_sq [0][t] = 0; g_sq [1][t] = 0;
}

// ---------------- pack weights: sign bits + per-tap popcounts ------------
// w layout OIHW: idx = oc*2304 + ic*9 + (ky*3+kx). block = (32,9), one block per (oc,set)
__global__ void pack_w_kernel(const float* __restrict__ w1,
                              const float* __restrict__ w2) {
    int oc    = blockIdx.x;
    int which = blockIdx.y;
    const float* w = which ? w2 : w1;
    int tap  = threadIdx.y;          // 0..8
    int lane = threadIdx.x;          // 0..31
    int pwt = 0;
    #pragma unroll
    for (int j = 0; j < CW; j++) {
        float v = w[oc*2304 + (j*32 + lane)*9 + tap];
        unsigned word = __ballot_sync(0xffffffffu, v > 0.0f);
        if (lane == 0) g_wb[which][oc*72 + tap*8 + j] = word;
        pwt += __popc(word);
    }
    if (lane == 0) g_pw[which][oc*9 + tap] = pwt;
}

// ---------------- pack activation signs -----------------------------------
// block per (h, n); 256 threads. src is NCHW fp32. Writes g_bits[n][h][w][cw].
__global__ void pack_sign_kernel(const float* __restrict__ src, int from_g) {
    __shared__ unsigned char s[CC*WW];      // 7168 sign bytes
    int h = blockIdx.x, n = blockIdx.y;
    const float* sp = from_g ? g_out1 : src;
    int basen = n * (CC*PIX);
    #pragma unroll
    for (int k = 0; k < 28; k++) {
        int e = threadIdx.x + k*256;         // e = c*28 + w
        int c = e / 28, w = e - c*28;
        float v = sp[basen + c*PIX + h*WW + w];
        s[e] = (v > 0.0f) ? 1 : 0;
    }
    __syncthreads();
    int warp = threadIdx.x >> 5, lane = threadIdx.x & 31;   // warp = channel word
    #pragma unroll
    for (int w = 0; w < 28; w++) {
        unsigned pred = s[(warp*32 + lane)*28 + w];
        unsigned word = __ballot_sync(0xffffffffu, pred != 0);
        if (lane == w) g_bits[n*(PIX*CW) + (h*WW + w)*CW + warp] = word;
    }
}

// ---------------- XNOR-popcount conv --------------------------------------
// block = 128 threads, handles (n, 4 rows, 64-oc chunk).
// smem: weights re-laid [g][t][o][k] for 4-oc groups; act tile swizzled
// [row][j4][col(pad32)][k] so per-lane LDS.128 is conflict-free; adj table
// folds boundary correction + valid-count constant.
#define SMEM_W_U32  (OCCH*72)                 // 4608
#define SMEM_A_U32  (6*2*32*4)                // 1536
#define SMEM_ADJ    (OCCH*9)                  // 576
#define SMEM_U32    (SMEM_W_U32 + SMEM_A_U32 + SMEM_ADJ)

__global__ void __launch_bounds__(128, 6) conv_kernel(int which) {
    extern __shared__ uint32_t sh[];
    uint32_t* s_w  = sh;                              // [g][t=tap*2+j4][o][k]
    uint32_t* s_a  = sh + SMEM_W_U32;                 // [row][j4][col][k]
    int*      s_adj = (int*)(sh + SMEM_W_U32 + SMEM_A_U32);

    const int n   = blockIdx.y;
    const int h0  = blockIdx.x * TH;
    const int oc0 = blockIdx.z * OCCH;
    const int tid = threadIdx.x;

    // weights, re-laid for 4-oc group broadcast reads
    const uint32_t* wb = g_wb[which];
    for (int i = tid; i < SMEM_W_U32; i += 128) {
        int g   = i / 288, rem = i - g*288;
        int t   = rem >> 4;
        int o   = (rem >> 2) & 3;
        int k   = rem & 3;
        int tap = t >> 1, j4 = t & 1;
        s_w[i] = wb[(oc0 + g*4 + o)*72 + tap*8 + j4*4 + k];
    }
    // activation tile rows h0-1..h0+4, cols padded (col = w_orig+1, col 0/29..31 zero)
    for (int i = tid; i < SMEM_A_U32; i += 128) {
        int k   = i & 3;
        int col = (i >> 2) & 31;
        int j4  = (i >> 7) & 1;
        int row = i >> 8;
        int hh  = h0 - 1 + row;
        int wo  = col - 1;
        uint32_t v = 0;
        if (hh >= 0 && hh < HH && wo >= 0 && wo < WW)
            v = g_bits[n*(PIX*CW) + (hh*WW + wo)*CW + j4*4 + k];
        s_a[i] = v;
    }
    // adj[oc][combo] = 256*nvalid + 2*corr  (combo = rowstate*3 + colstate)
    const int* pw = g_pw[which] + oc0*9;
    for (int e = tid; e < SMEM_ADJ; e += 128) {
        int ocl = e / 9, combo = e - ocl*9;
        int rs = combo / 3, cs = combo - rs*3;
        const int* pwo = pw + ocl*9;
        int corr = 0;
        if (rs) { int ir = (rs == 1) ? 0 : 2;
                  corr += pwo[ir*3] + pwo[ir*3+1] + pwo[ir*3+2]; }
        if (cs) { int ic = (cs == 1) ? 0 : 2;
                  corr += pwo[ic] + pwo[3+ic] + pwo[6+ic]; }
        if (rs && cs) { int ir = (rs == 1) ? 0 : 2, ic = (cs == 1) ? 0 : 2;
                        corr -= pwo[ir*3 + ic]; }
        int nv = (rs ? 2 : 3) * (cs ? 2 : 3);
        s_adj[e] = CC*nv + 2*corr;
    }
    __syncthreads();

    if (tid >= TH*WW) return;          // 112 workers

    const int r = tid / WW;
    const int w = tid - r*WW;
    const int h = h0 + r;
    const int rs = (h == 0) ? 1 : ((h == HH-1) ? 2 : 0);
    const int cs = (w == 0) ? 1 : ((w == WW-1) ? 2 : 0);
    const int combo = rs*3 + cs;

    short* yout = g_y + (size_t)n*(CC*PIX) + (size_t)oc0*PIX + h0*WW + tid;

    for (int g = 0; g < NG; g++) {
        int acc0 = 0, acc1 = 0, acc2 = 0, acc3 = 0;
        const uint4* wq = (const uint4*)s_w + g*(18*4);
        #pragma unroll
        for (int ky = 0; ky < 3; ky++) {
            #pragma unroll
            for (int j4 = 0; j4 < 2; j4++) {
                const uint4* ap = (const uint4*)s_a + (((r + ky)*2 + j4)*32 + w);
                uint4 A0 = ap[0], A1 = ap[1], A2 = ap[2];
                #pragma unroll
                for (int kx = 0; kx < 3; kx++) {
                    uint4 A = (kx == 0) ? A0 : ((kx == 1) ? A1 : A2);
                    const uint4* wt = wq + ((ky*3 + kx)*2 + j4)*4;
                    uint4 W;
                    W = wt[0];
                    acc0 += __popc(A.x^W.x) + __popc(A.y^W.y) + __popc(A.z^W.z) + __popc(A.w^W.w);
                    W = wt[1];
                    acc1 += __popc(A.x^W.x) + __popc(A.y^W.y) + __popc(A.z^W.z) + __popc(A.w^W.w);
                    W = wt[2];
                    acc2 += __popc(A.x^W.x) + __popc(A.y^W.y) + __popc(A.z^W.z) + __popc(A.w^W.w);
                    W = wt[3];
                    acc3 += __popc(A.x^W.x) + __popc(A.y^W.y) + __popc(A.z^W.z) + __popc(A.w^W.w);
                }
            }
        }
        const int* adj = s_adj + (g*4)*9 + combo;
        yout[(g*4 + 0)*PIX] = (short)(adj[0]  - 2*acc0);
        yout[(g*4 + 1)*PIX] = (short)(adj[9]  - 2*acc1);
        yout[(g*4 + 2)*PIX] = (short)(adj[18] - 2*acc2);
        yout[(g*4 + 3)*PIX] = (short)(adj[27] - 2*acc3);
    }
}

// ---------------- stats reduction over g_y (exact integer sums) -----------
// grid (CC, 8): block handles channel oc over 8 batch images.
__global__ void __launch_bounds__(256) redstats_kernel(int which) {
    const int oc = blockIdx.x, ns = blockIdx.y;
    int s1 = 0, s2 = 0;        // per-thread: <=26 elems; s2 <= 26*2304^2 < 2^31
    for (int i = threadIdx.x; i < 8*392; i += 256) {
        int nn = i / 392, j = i - nn*392;
        const short2* p = (const short2*)(g_y + (((size_t)(ns*8 + nn))*CC + oc)*PIX);
        short2 v = p[j];
        int a = v.x, b = v.y;
        s1 += a + b;
        s2 += a*a + b*b;
    }
    // warp-reduce s1 (safe in int); s2 goes per-thread to 64-bit atomic
    int w1 = __reduce_add_sync(0xffffffffu, s1);
    if ((threadIdx.x & 31) == 0) atomicAdd(&g_sum[which][oc], w1);
    atomicAdd(&g_sq[which][oc], (unsigned long long)(long long)s2);
}

// ---------------- BN statistics -> scale/shift -----------------------------
__global__ void stats_kernel(int which, const float* __restrict__ gamma,
                             const float* __restrict__ beta) {
    int c = threadIdx.x;                       // 256 threads
    double m   = (double)g_sum[which][c] / (double)NPIX;
    double ex2 = (double)g_sq [which][c] / (double)NPIX;
    double var = ex2 - m*m;
    double inv = rsqrt(var + 1e-5);
    double gs  = (double)gamma[c] * inv;
    g_scale[which][c] = (float)gs;
    g_shift[which][c] = (float)((double)beta[c] - m * gs);
}

// ---------------- BN apply + residual + hardtanh ---------------------------
__global__ void __launch_bounds__(256) bnres_kernel(int which,
                                                    const float* __restrict__ res_in,
                                                    float* __restrict__ dst_out) {
    int idx = blockIdx.x * 256 + threadIdx.x;      // grid sized exactly to TOT
    int c = (idx / PIX) & (CC - 1);
    float v = fmaf((float)g_y[idx], g_scale[which][c], g_shift[which][c]);
    const float* res = (which == 0) ? res_in : g_out1;
    v += res[idx];
    v = fminf(1.0f, fmaxf(-1.0f, v));
    if (which == 0) g_out1[idx] = v;
    else            dst_out[idx] = v;
}

// ---------------- launcher -------------------------------------------------
extern "C" void kernel_launch(void* const* d_in, const int* in_sizes, int n_in,
                              void* d_out, int out_size) {
    const float* x      = (const float*)d_in[0];
    const float* w1     = (const float*)d_in[1];
    const float* gamma1 = (const float*)d_in[2];
    const float* beta1  = (const float*)d_in[3];
    const float* w2     = (const float*)d_in[4];
    const float* gamma2 = (const float*)d_in[5];
    const float* beta2  = (const float*)d_in[6];
    float* out = (float*)d_out;

    constexpr int SMEM_BYTES = SMEM_U32 * 4;       // 26,880 B (< 48KB default)

    zero_kernel<<<1, 256>>>();
    pack_w_kernel<<<dim3(CC, 2), dim3(32, 9)>>>(w1, w2);

    // stage 1
    pack_sign_kernel<<<dim3(HH, NB), 256>>>(x, 0);
    conv_kernel<<<dim3(HH/TH, NB, NCH), 128, SMEM_BYTES>>>(0);
    redstats_kernel<<<dim3(CC, NB/8), 256>>>(0);
    stats_kernel<<<1, 256>>>(0, gamma1, beta1);
    bnres_kernel<<<TOT/256, 256>>>(0, x, nullptr);

    // stage 2
    pack_sign_kernel<<<dim3(HH, NB), 256>>>(nullptr, 1);
    conv_kernel<<<dim3(HH/TH, NB, NCH), 128, SMEM_BYTES>>>(1);
    redstats_kernel<<<dim3(CC, NB/8), 256>>>(1);
    stats_kernel<<<1, 256>>>(1, gamma2, beta2);
    bnres_kernel<<<TOT/256, 256>>>(1, nullptr, out);
}

// round 7
// speedup vs baseline: 1.2544x; 1.2544x over previous
#include <cuda_runtime.h>
#include <cstdint>

// Problem constants
#define NB   64          // batch
#define CC   256         // channels
#define HH   28
#define WW   28
#define PIX  (HH*WW)                 // 784
#define NPIX (NB*PIX)                // 50176
#define TOT  (NB*CC*PIX)             // 12,845,056
#define CW   8                       // 256 channels / 32 bits
#define TH   4                       // rows per conv block
#define OCCH 32                      // output channels per block (oc chunk)
#define NCH  (CC/OCCH)               // 8 chunks
#define NG   (OCCH/4)                // 8 groups of 4 ocs

// ---------------- scratch (device globals; no allocation allowed) --------
__device__ uint32_t g_bits[NB*PIX*CW];            // packed activation signs
__device__ uint32_t g_wb[2][CC*72];               // packed weight signs: [oc][tap][word]
__device__ int      g_pw[2][CC*9];                // popcount of each weight tap
__device__ short    g_y[TOT];                     // integer conv output
__device__ float    g_out1[TOT];                  // stage-1 output (residual for stage 2)
__device__ float    g_scale[2][CC], g_shift[2][CC];

// ---------------- pack weights: sign bits + per-tap popcounts ------------
// w layout OIHW: idx = oc*2304 + ic*9 + (ky*3+kx). block = (32,9), one block per (oc,set)
__global__ void pack_w_kernel(const float* __restrict__ w1,
                              const float* __restrict__ w2) {
    int oc    = blockIdx.x;
    int which = blockIdx.y;
    const float* w = which ? w2 : w1;
    int tap  = threadIdx.y;          // 0..8
    int lane = threadIdx.x;          // 0..31
    int pwt = 0;
    #pragma unroll
    for (int j = 0; j < CW; j++) {
        float v = w[oc*2304 + (j*32 + lane)*9 + tap];
        unsigned word = __ballot_sync(0xffffffffu, v > 0.0f);
        if (lane == 0) g_wb[which][oc*72 + tap*8 + j] = word;
        pwt += __popc(word);
    }
    if (lane == 0) g_pw[which][oc*9 + tap] = pwt;
}

// ---------------- pack activation signs -----------------------------------
// block per (h, n); 256 threads. src is NCHW fp32. Writes g_bits[n][h][w][cw].
__global__ void pack_sign_kernel(const float* __restrict__ src, int from_g) {
    __shared__ unsigned char s[CC*WW];      // 7168 sign bytes
    int h = blockIdx.x, n = blockIdx.y;
    const float* sp = from_g ? g_out1 : src;
    int basen = n * (CC*PIX);
    #pragma unroll
    for (int k = 0; k < 28; k++) {
        int e = threadIdx.x + k*256;         // e = c*28 + w
        int c = e / 28, w = e - c*28;
        float v = sp[basen + c*PIX + h*WW + w];
        s[e] = (v > 0.0f) ? 1 : 0;
    }
    __syncthreads();
    int warp = threadIdx.x >> 5, lane = threadIdx.x & 31;   // warp = channel word
    #pragma unroll
    for (int w = 0; w < 28; w++) {
        unsigned pred = s[(warp*32 + lane)*28 + w];
        unsigned word = __ballot_sync(0xffffffffu, pred != 0);
        if (lane == w) g_bits[n*(PIX*CW) + (h*WW + w)*CW + warp] = word;
    }
}

// ---------------- XNOR-popcount conv --------------------------------------
// block = 128 threads, handles (n, 4 rows, 32-oc chunk).
// smem: weights re-laid [g][t][o][k] for 4-oc groups; act tile swizzled
// [row][j4][col(pad32)][4] so per-lane LDS.128 is conflict-free; adj table
// folds boundary correction + valid-count constant.
#define SMEM_W_U32  (OCCH*72)                 // 2304
#define SMEM_A_U32  (6*2*32*4)                // 1536
#define SMEM_ADJ    (OCCH*9)                  // 288
#define SMEM_U32    (SMEM_W_U32 + SMEM_A_U32 + SMEM_ADJ)

__global__ void __launch_bounds__(128, 8) conv_kernel(int which) {
    extern __shared__ uint32_t sh[];
    uint32_t* s_w  = sh;                              // [g][t=tap*2+j4][o][k]
    uint32_t* s_a  = sh + SMEM_W_U32;                 // [row][j4][col][k]
    int*      s_adj = (int*)(sh + SMEM_W_U32 + SMEM_A_U32);

    const int n   = blockIdx.y;
    const int h0  = blockIdx.x * TH;
    const int oc0 = blockIdx.z * OCCH;
    const int tid = threadIdx.x;

    // weights, re-laid for 4-oc group broadcast reads
    const uint32_t* wb = g_wb[which];
    for (int i = tid; i < SMEM_W_U32; i += 128) {
        int g   = i / 288, rem = i - g*288;
        int t   = rem >> 4;
        int o   = (rem >> 2) & 3;
        int k   = i & 3;
        int tap = t >> 1, j4 = t & 1;
        s_w[i] = wb[(oc0 + g*4 + o)*72 + tap*8 + j4*4 + k];
    }
    // activation tile rows h0-1..h0+4, cols padded (col = w_orig+1, col 0/29..31 zero)
    for (int i = tid; i < SMEM_A_U32; i += 128) {
        int k   = i & 3;
        int col = (i >> 2) & 31;
        int j4  = (i >> 7) & 1;
        int row = i >> 8;
        int hh  = h0 - 1 + row;
        int wo  = col - 1;
        uint32_t v = 0;
        if (hh >= 0 && hh < HH && wo >= 0 && wo < WW)
            v = g_bits[n*(PIX*CW) + (hh*WW + wo)*CW + j4*4 + k];
        s_a[i] = v;
    }
    // adj[oc][combo] = 256*nvalid + 2*corr  (combo = rowstate*3 + colstate)
    const int* pw = g_pw[which] + oc0*9;
    for (int e = tid; e < SMEM_ADJ; e += 128) {
        int ocl = e / 9, combo = e - ocl*9;
        int rs = combo / 3, cs = combo - rs*3;
        const int* pwo = pw + ocl*9;
        int corr = 0;
        if (rs) { int ir = (rs == 1) ? 0 : 2;
                  corr += pwo[ir*3] + pwo[ir*3+1] + pwo[ir*3+2]; }
        if (cs) { int ic = (cs == 1) ? 0 : 2;
                  corr += pwo[ic] + pwo[3+ic] + pwo[6+ic]; }
        if (rs && cs) { int ir = (rs == 1) ? 0 : 2, ic = (cs == 1) ? 0 : 2;
                        corr -= pwo[ir*3 + ic]; }
        int nv = (rs ? 2 : 3) * (cs ? 2 : 3);
        s_adj[e] = CC*nv + 2*corr;
    }
    __syncthreads();

    if (tid >= TH*WW) return;          // 112 workers

    const int r = tid / WW;
    const int w = tid - r*WW;
    const int h = h0 + r;
    const int rs = (h == 0) ? 1 : ((h == HH-1) ? 2 : 0);
    const int cs = (w == 0) ? 1 : ((w == WW-1) ? 2 : 0);
    const int combo = rs*3 + cs;

    short* yout = g_y + (size_t)n*(CC*PIX) + (size_t)oc0*PIX + h0*WW + tid;

    #pragma unroll 2
    for (int g = 0; g < NG; g++) {
        int acc0 = 0, acc1 = 0, acc2 = 0, acc3 = 0;
        const uint4* wq = (const uint4*)s_w + g*(18*4);
        #pragma unroll
        for (int ky = 0; ky < 3; ky++) {
            #pragma unroll
            for (int j4 = 0; j4 < 2; j4++) {
                const uint4* ap = (const uint4*)s_a + (((r + ky)*2 + j4)*32 + w);
                uint4 A0 = ap[0], A1 = ap[1], A2 = ap[2];
                #pragma unroll
                for (int kx = 0; kx < 3; kx++) {
                    uint4 A = (kx == 0) ? A0 : ((kx == 1) ? A1 : A2);
                    const uint4* wt = wq + ((ky*3 + kx)*2 + j4)*4;
                    uint4 W;
                    W = wt[0];
                    acc0 += __popc(A.x^W.x) + __popc(A.y^W.y) + __popc(A.z^W.z) + __popc(A.w^W.w);
                    W = wt[1];
                    acc1 += __popc(A.x^W.x) + __popc(A.y^W.y) + __popc(A.z^W.z) + __popc(A.w^W.w);
                    W = wt[2];
                    acc2 += __popc(A.x^W.x) + __popc(A.y^W.y) + __popc(A.z^W.z) + __popc(A.w^W.w);
                    W = wt[3];
                    acc3 += __popc(A.x^W.x) + __popc(A.y^W.y) + __popc(A.z^W.z) + __popc(A.w^W.w);
                }
            }
        }
        const int* adj = s_adj + (g*4)*9 + combo;
        yout[(g*4 + 0)*PIX] = (short)(adj[0]  - 2*acc0);
        yout[(g*4 + 1)*PIX] = (short)(adj[9]  - 2*acc1);
        yout[(g*4 + 2)*PIX] = (short)(adj[18] - 2*acc2);
        yout[(g*4 + 3)*PIX] = (short)(adj[27] - 2*acc3);
    }
}

// ---------------- per-channel stats -> scale/shift (no atomics) -----------
// one block per channel: exact integer sums over N,H,W, then BN coefficients.
__global__ void __launch_bounds__(256) chanstats_kernel(int which,
                                                        const float* __restrict__ gamma,
                                                        const float* __restrict__ beta) {
    const int oc = blockIdx.x;
    long long s1 = 0, s2 = 0;
    for (int i = threadIdx.x; i < NB*392; i += 256) {
        int nn = i / 392, j = i - nn*392;
        short2 v = ((const short2*)(g_y + ((size_t)(nn*CC + oc))*PIX))[j];
        int a = v.x, b = v.y;
        s1 += a + b;
        s2 += a*a + b*b;
    }
    #pragma unroll
    for (int o = 16; o; o >>= 1) {
        s1 += __shfl_down_sync(0xffffffffu, s1, o);
        s2 += __shfl_down_sync(0xffffffffu, s2, o);
    }
    __shared__ long long sh1[8], sh2[8];
    int warp = threadIdx.x >> 5, lane = threadIdx.x & 31;
    if (lane == 0) { sh1[warp] = s1; sh2[warp] = s2; }
    __syncthreads();
    if (threadIdx.x == 0) {
        long long t1 = 0, t2 = 0;
        #pragma unroll
        for (int k = 0; k < 8; k++) { t1 += sh1[k]; t2 += sh2[k]; }
        double m   = (double)t1 / (double)NPIX;
        double ex2 = (double)t2 / (double)NPIX;
        double var = ex2 - m*m;
        double inv = rsqrt(var + 1e-5);
        double gs  = (double)gamma[oc] * inv;
        g_scale[which][oc] = (float)gs;
        g_shift[which][oc] = (float)((double)beta[oc] - m * gs);
    }
}

// ---------------- BN apply + residual + hardtanh ---------------------------
__global__ void __launch_bounds__(256) bnres_kernel(int which,
                                                    const float* __restrict__ res_in,
                                                    float* __restrict__ dst_out) {
    int idx = blockIdx.x * 256 + threadIdx.x;      // grid sized exactly to TOT
    int c = (idx / PIX) & (CC - 1);
    float v = fmaf((float)g_y[idx], g_scale[which][c], g_shift[which][c]);
    const float* res = (which == 0) ? res_in : g_out1;
    v += res[idx];
    v = fminf(1.0f, fmaxf(-1.0f, v));
    if (which == 0) g_out1[idx] = v;
    else            dst_out[idx] = v;
}

// ---------------- launcher -------------------------------------------------
extern "C" void kernel_launch(void* const* d_in, const int* in_sizes, int n_in,
                              void* d_out, int out_size) {
    const float* x      = (const float*)d_in[0];
    const float* w1     = (const float*)d_in[1];
    const float* gamma1 = (const float*)d_in[2];
    const float* beta1  = (const float*)d_in[3];
    const float* w2     = (const float*)d_in[4];
    const float* gamma2 = (const float*)d_in[5];
    const float* beta2  = (const float*)d_in[6];
    float* out = (float*)d_out;

    constexpr int SMEM_BYTES = SMEM_U32 * 4;       // 16,512 B

    pack_w_kernel<<<dim3(CC, 2), dim3(32, 9)>>>(w1, w2);

    // stage 1
    pack_sign_kernel<<<dim3(HH, NB), 256>>>(x, 0);
    conv_kernel<<<dim3(HH/TH, NB, NCH), 128, SMEM_BYTES>>>(0);
    chanstats_kernel<<<CC, 256>>>(0, gamma1, beta1);
    bnres_kernel<<<TOT/256, 256>>>(0, x, nullptr);

    // stage 2
    pack_sign_kernel<<<dim3(HH, NB), 256>>>(nullptr, 1);
    conv_kernel<<<dim3(HH/TH, NB, NCH), 128, SMEM_BYTES>>>(1);
    chanstats_kernel<<<CC, 256>>>(1, gamma2, beta2);
    bnres_kernel<<<TOT/256, 256>>>(1, nullptr, out);
}

// round 8
// speedup vs baseline: 1.7771x; 1.4167x over previous
#include <cuda_runtime.h>
#include <cstdint>

// Problem constants
#define NB   64          // batch
#define CC   256         // channels
#define HH   28
#define WW   28
#define PIX  (HH*WW)                 // 784
#define NPIX (NB*PIX)                // 50176
#define TOT  (NB*CC*PIX)             // 12,845,056
#define CW   8                       // 256 channels / 32 bits
#define TH   4                       // rows per conv block
#define OCCH 32                      // output channels per block (oc chunk)
#define NCH  (CC/OCCH)               // 8 chunks
#define NG   (OCCH/4)                // 8 groups of 4 ocs

// ---------------- scratch (device globals; no allocation allowed) --------
__device__ uint32_t g_bits[NB*PIX*CW];            // packed activation signs
__device__ uint32_t g_wb[2][CC*72];               // packed weight signs: [oc][tap][word]
__device__ int      g_pw[2][CC*9];                // popcount of each weight tap
__device__ short    g_y[TOT];                     // integer conv output
__device__ float    g_out1[TOT];                  // stage-1 output (residual for stage 2)
__device__ float    g_scale[2][CC], g_shift[2][CC];

// ---------------- pack weights: sign bits + per-tap popcounts ------------
__global__ void pack_w_kernel(const float* __restrict__ w1,
                              const float* __restrict__ w2) {
    int oc    = blockIdx.x;
    int which = blockIdx.y;
    const float* w = which ? w2 : w1;
    int tap  = threadIdx.y;          // 0..8
    int lane = threadIdx.x;          // 0..31
    int pwt = 0;
    #pragma unroll
    for (int j = 0; j < CW; j++) {
        float v = w[oc*2304 + (j*32 + lane)*9 + tap];
        unsigned word = __ballot_sync(0xffffffffu, v > 0.0f);
        if (lane == 0) g_wb[which][oc*72 + tap*8 + j] = word;
        pwt += __popc(word);
    }
    if (lane == 0) g_pw[which][oc*9 + tap] = pwt;
}

// ---------------- pack activation signs -----------------------------------
__global__ void pack_sign_kernel(const float* __restrict__ src, int from_g) {
    __shared__ unsigned char s[CC*WW];      // 7168 sign bytes
    int h = blockIdx.x, n = blockIdx.y;
    const float* sp = from_g ? g_out1 : src;
    int basen = n * (CC*PIX);
    #pragma unroll
    for (int k = 0; k < 28; k++) {
        int e = threadIdx.x + k*256;         // e = c*28 + w
        int c = e / 28, w = e - c*28;
        float v = sp[basen + c*PIX + h*WW + w];
        s[e] = (v > 0.0f) ? 1 : 0;
    }
    __syncthreads();
    int warp = threadIdx.x >> 5, lane = threadIdx.x & 31;   // warp = channel word
    #pragma unroll
    for (int w = 0; w < 28; w++) {
        unsigned pred = s[(warp*32 + lane)*28 + w];
        unsigned word = __ballot_sync(0xffffffffu, pred != 0);
        if (lane == w) g_bits[n*(PIX*CW) + (h*WW + w)*CW + warp] = word;
    }
}

// ---------------- XNOR conv via CSA-compressed popcount -------------------
// Per (oc, tap): 8 XOR words compressed by 3 full adders into 5 popc words
// (weights 1,1 and 2,2,2). Rebalances POPC pipe (quarter-rate) vs LOP3 pipe.
#define SMEM_W_U32  (OCCH*72)                 // 2304  [g][tap][o][j]
#define SMEM_A_U32  (6*2*32*4)                // 1536  [row][half][col][k]
#define SMEM_ADJ    (OCCH*9)                  // 288
#define SMEM_U32    (SMEM_W_U32 + SMEM_A_U32 + SMEM_ADJ)

#define FA(x, y, z, s, c)  { s = (x)^(y)^(z); c = ((x)&(y)) | ((z)&((x)|(y))); }

__global__ void __launch_bounds__(128, 6) conv_kernel(int which) {
    extern __shared__ uint32_t sh[];
    uint32_t* s_w  = sh;                              // [g][tap][o][j0..7]
    uint32_t* s_a  = sh + SMEM_W_U32;                 // [row][half][col][k]
    int*      s_adj = (int*)(sh + SMEM_W_U32 + SMEM_A_U32);

    const int n   = blockIdx.y;
    const int h0  = blockIdx.x * TH;
    const int oc0 = blockIdx.z * OCCH;
    const int tid = threadIdx.x;

    // weights: [g][tap][o][j] for broadcast LDS.128 pairs
    const uint32_t* wb = g_wb[which];
    for (int i = tid; i < SMEM_W_U32; i += 128) {
        int j   = i & 7;
        int o   = (i >> 3) & 3;
        int rem = i % 288;
        int tap = rem >> 5;
        int g   = i / 288;
        s_w[i] = wb[(oc0 + g*4 + o)*72 + tap*8 + j];
    }
    // activation tile rows h0-1..h0+4, cols padded (col = w_orig+1)
    for (int i = tid; i < SMEM_A_U32; i += 128) {
        int k    = i & 3;
        int col  = (i >> 2) & 31;
        int half = (i >> 7) & 1;
        int row  = i >> 8;
        int hh   = h0 - 1 + row;
        int wo   = col - 1;
        uint32_t v = 0;
        if (hh >= 0 && hh < HH && wo >= 0 && wo < WW)
            v = g_bits[n*(PIX*CW) + (hh*WW + wo)*CW + half*4 + k];
        s_a[i] = v;
    }
    // adj[oc][combo] = 256*nvalid + 2*corr
    const int* pw = g_pw[which] + oc0*9;
    for (int e = tid; e < SMEM_ADJ; e += 128) {
        int ocl = e / 9, combo = e - ocl*9;
        int rs = combo / 3, cs = combo - rs*3;
        const int* pwo = pw + ocl*9;
        int corr = 0;
        if (rs) { int ir = (rs == 1) ? 0 : 2;
                  corr += pwo[ir*3] + pwo[ir*3+1] + pwo[ir*3+2]; }
        if (cs) { int ic = (cs == 1) ? 0 : 2;
                  corr += pwo[ic] + pwo[3+ic] + pwo[6+ic]; }
        if (rs && cs) { int ir = (rs == 1) ? 0 : 2, ic = (cs == 1) ? 0 : 2;
                        corr -= pwo[ir*3 + ic]; }
        int nv = (rs ? 2 : 3) * (cs ? 2 : 3);
        s_adj[e] = CC*nv + 2*corr;
    }
    __syncthreads();

    if (tid >= TH*WW) return;          // 112 workers

    const int r = tid / WW;
    const int w = tid - r*WW;
    const int h = h0 + r;
    const int rs = (h == 0) ? 1 : ((h == HH-1) ? 2 : 0);
    const int cs = (w == 0) ? 1 : ((w == WW-1) ? 2 : 0);
    const int combo = rs*3 + cs;

    short* yout = g_y + (size_t)n*(CC*PIX) + (size_t)oc0*PIX + h0*WW + tid;

    for (int g = 0; g < NG; g++) {
        int acc1_0 = 0, acc1_1 = 0, acc1_2 = 0, acc1_3 = 0;   // weight-1 popcs
        int acc2_0 = 0, acc2_1 = 0, acc2_2 = 0, acc2_3 = 0;   // weight-2 popcs
        const uint4* wq = (const uint4*)s_w + g*72;            // [tap][o][lo/hi]
        #pragma unroll
        for (int ky = 0; ky < 3; ky++) {
            const uint4* apL = (const uint4*)s_a + (((r + ky)*2 + 0)*32 + w);
            const uint4* apH = (const uint4*)s_a + (((r + ky)*2 + 1)*32 + w);
            uint4 L0 = apL[0], L1 = apL[1], L2 = apL[2];
            uint4 H0 = apH[0], H1 = apH[1], H2 = apH[2];
            #pragma unroll
            for (int kx = 0; kx < 3; kx++) {
                uint4 AL = (kx == 0) ? L0 : ((kx == 1) ? L1 : L2);
                uint4 AH = (kx == 0) ? H0 : ((kx == 1) ? H1 : H2);
                const uint4* wt = wq + (ky*3 + kx)*8;
                #pragma unroll
                for (int o = 0; o < 4; o++) {
                    uint4 WL = wt[o*2], WH = wt[o*2 + 1];
                    uint32_t v0 = AL.x ^ WL.x, v1 = AL.y ^ WL.y;
                    uint32_t v2 = AL.z ^ WL.z, v3 = AL.w ^ WL.w;
                    uint32_t v4 = AH.x ^ WH.x, v5 = AH.y ^ WH.y;
                    uint32_t v6 = AH.z ^ WH.z, v7 = AH.w ^ WH.w;
                    uint32_t sA, cA, sB, cB, S, C;
                    FA(v0, v1, v2, sA, cA);
                    FA(v3, v4, v5, sB, cB);
                    FA(sA, sB, v6, S, C);
                    int p1 = __popc(S) + __popc(v7);
                    int p2 = __popc(cA) + __popc(cB) + __popc(C);
                    if (o == 0) { acc1_0 += p1; acc2_0 += p2; }
                    if (o == 1) { acc1_1 += p1; acc2_1 += p2; }
                    if (o == 2) { acc1_2 += p1; acc2_2 += p2; }
                    if (o == 3) { acc1_3 += p1; acc2_3 += p2; }
                }
            }
        }
        const int* adj = s_adj + (g*4)*9 + combo;
        yout[(g*4 + 0)*PIX] = (short)(adj[0]  - 2*(acc1_0 + 2*acc2_0));
        yout[(g*4 + 1)*PIX] = (short)(adj[9]  - 2*(acc1_1 + 2*acc2_1));
        yout[(g*4 + 2)*PIX] = (short)(adj[18] - 2*(acc1_2 + 2*acc2_2));
        yout[(g*4 + 3)*PIX] = (short)(adj[27] - 2*(acc1_3 + 2*acc2_3));
    }
}

// ---------------- per-channel stats -> scale/shift (no atomics) -----------
__global__ void __launch_bounds__(512) chanstats_kernel(int which,
                                                        const float* __restrict__ gamma,
                                                        const float* __restrict__ beta) {
    const int oc = blockIdx.x;
    int s1 = 0, s2 = 0;     // per-thread ≤25 short4: |s1|≤230K, s2≤531M < 2^31
    for (int i = threadIdx.x; i < NB*196; i += 512) {
        int nn = i / 196, j = i - nn*196;
        short4 v = ((const short4*)(g_y + ((size_t)(nn*CC + oc))*PIX))[j];
        int a = v.x, b = v.y, c = v.z, d = v.w;
        s1 += (a + b) + (c + d);
        s2 += (a*a + b*b) + (c*c + d*d);
    }
    long long l1 = s1, l2 = s2;
    #pragma unroll
    for (int o = 16; o; o >>= 1) {
        l1 += __shfl_down_sync(0xffffffffu, l1, o);
        l2 += __shfl_down_sync(0xffffffffu, l2, o);
    }
    __shared__ long long sh1[16], sh2[16];
    int warp = threadIdx.x >> 5, lane = threadIdx.x & 31;
    if (lane == 0) { sh1[warp] = l1; sh2[warp] = l2; }
    __syncthreads();
    if (threadIdx.x == 0) {
        long long t1 = 0, t2 = 0;
        #pragma unroll
        for (int k = 0; k < 16; k++) { t1 += sh1[k]; t2 += sh2[k]; }
        double m   = (double)t1 / (double)NPIX;
        double ex2 = (double)t2 / (double)NPIX;
        double var = ex2 - m*m;
        double inv = rsqrt(var + 1e-5);
        double gs  = (double)gamma[oc] * inv;
        g_scale[which][oc] = (float)gs;
        g_shift[which][oc] = (float)((double)beta[oc] - m * gs);
    }
}

// ---------------- BN apply + residual + hardtanh (vectorized) -------------
__global__ void __launch_bounds__(256) bnres_kernel(int which,
                                                    const float* __restrict__ res_in,
                                                    float* __restrict__ dst_out) {
    int idx4 = blockIdx.x * 256 + threadIdx.x;     // grid = TOT/1024
    int base = idx4 << 2;
    int c = (base / PIX) & (CC - 1);               // 4-elem chunk never crosses channel
    float sc = g_scale[which][c], sf = g_shift[which][c];
    short4 yv = ((const short4*)g_y)[idx4];
    const float* res = (which == 0) ? res_in : g_out1;
    float4 rv = ((const float4*)res)[idx4];
    float4 o;
    o.x = fminf(1.0f, fmaxf(-1.0f, fmaf((float)yv.x, sc, sf) + rv.x));
    o.y = fminf(1.0f, fmaxf(-1.0f, fmaf((float)yv.y, sc, sf) + rv.y));
    o.z = fminf(1.0f, fmaxf(-1.0f, fmaf((float)yv.z, sc, sf) + rv.z));
    o.w = fminf(1.0f, fmaxf(-1.0f, fmaf((float)yv.w, sc, sf) + rv.w));
    if (which == 0) ((float4*)g_out1)[idx4] = o;
    else            ((float4*)dst_out)[idx4] = o;
}

// ---------------- launcher -------------------------------------------------
extern "C" void kernel_launch(void* const* d_in, const int* in_sizes, int n_in,
                              void* d_out, int out_size) {
    const float* x      = (const float*)d_in[0];
    const float* w1     = (const float*)d_in[1];
    const float* gamma1 = (const float*)d_in[2];
    const float* beta1  = (const float*)d_in[3];
    const float* w2     = (const float*)d_in[4];
    const float* gamma2 = (const float*)d_in[5];
    const float* beta2  = (const float*)d_in[6];
    float* out = (float*)d_out;

    constexpr int SMEM_BYTES = SMEM_U32 * 4;       // 16,512 B

    pack_w_kernel<<<dim3(CC, 2), dim3(32, 9)>>>(w1, w2);

    // stage 1
    pack_sign_kernel<<<dim3(HH, NB), 256>>>(x, 0);
    conv_kernel<<<dim3(HH/TH, NB, NCH), 128, SMEM_BYTES>>>(0);
    chanstats_kernel<<<CC, 512>>>(0, gamma1, beta1);
    bnres_kernel<<<TOT/1024, 256>>>(0, x, nullptr);

    // stage 2
    pack_sign_kernel<<<dim3(HH, NB), 256>>>(nullptr, 1);
    conv_kernel<<<dim3(HH/TH, NB, NCH), 128, SMEM_BYTES>>>(1);
    chanstats_kernel<<<CC, 512>>>(1, gamma2, beta2);
    bnres_kernel<<<TOT/1024, 256>>>(1, nullptr, out);
}